// round 2
// baseline (speedup 1.0000x reference)
#include <cuda_runtime.h>
#include <math.h>

// ---------------------------------------------------------------------------
// Problem constants: B=2, S=2048, E=1024, H=16, D=64
// ---------------------------------------------------------------------------
#define BATCH 2
#define SEQ   2048
#define EMB   1024
#define HEADS 16
#define HDIM  64
#define ROWS  (BATCH * SEQ)        // 4096
#define QKV_N (3 * EMB)            // 3072

// Scratch (allocation-free rule: __device__ globals, referenced directly by
// symbol from device code -- no host API needed).
__device__ float g_qkv[ROWS * QKV_N];   // 48 MB
__device__ float g_attn[ROWS * EMB];    // 16 MB

// ---------------------------------------------------------------------------
// SGEMM with fused bias: C[M,N] = A[M,K] @ B[K,N] + bias[N]
// BM=BN=128, BK=8, 256 threads, 8x8 accum per thread, float4 everywhere.
// All dims here are multiples of the tile sizes -> no bounds checks.
// ---------------------------------------------------------------------------
__global__ __launch_bounds__(256) void sgemm_bias_kernel(
    int M, int N, int K,
    const float* __restrict__ A, const float* __restrict__ B,
    const float* __restrict__ bias, float* __restrict__ C)
{
    constexpr int BM = 128, BN = 128, BK = 8, TM = 8, TN = 8;
    __shared__ float As[BK][BM];
    __shared__ float Bs[BK][BN];

    const int tid  = threadIdx.x;
    const int cRow = blockIdx.y * BM;
    const int cCol = blockIdx.x * BN;

    // A tile (BM x BK): 256 float4s, one per thread; stored transposed.
    const int aRow = tid >> 1;            // 0..127
    const int aCol = (tid & 1) * 4;       // 0 or 4
    // B tile (BK x BN): 256 float4s, one per thread.
    const int bRow = tid >> 5;            // 0..7
    const int bCol = (tid & 31) * 4;      // 0..124

    const int tr = (tid >> 4) * TM;       // thread row in C tile
    const int tc = (tid & 15) * TN;       // thread col in C tile

    const float* Aptr = A + (long)cRow * K;
    const float* Bptr = B + cCol;

    float acc[TM][TN] = {};

    for (int k0 = 0; k0 < K; k0 += BK) {
        float4 av = *reinterpret_cast<const float4*>(Aptr + (long)aRow * K + k0 + aCol);
        As[aCol + 0][aRow] = av.x;
        As[aCol + 1][aRow] = av.y;
        As[aCol + 2][aRow] = av.z;
        As[aCol + 3][aRow] = av.w;
        *reinterpret_cast<float4*>(&Bs[bRow][bCol]) =
            *reinterpret_cast<const float4*>(Bptr + (long)(k0 + bRow) * N + bCol);
        __syncthreads();

        #pragma unroll
        for (int k = 0; k < BK; k++) {
            float regM[TM], regN[TN];
            *reinterpret_cast<float4*>(&regM[0]) = *reinterpret_cast<float4*>(&As[k][tr]);
            *reinterpret_cast<float4*>(&regM[4]) = *reinterpret_cast<float4*>(&As[k][tr + 4]);
            *reinterpret_cast<float4*>(&regN[0]) = *reinterpret_cast<float4*>(&Bs[k][tc]);
            *reinterpret_cast<float4*>(&regN[4]) = *reinterpret_cast<float4*>(&Bs[k][tc + 4]);
            #pragma unroll
            for (int i = 0; i < TM; i++)
                #pragma unroll
                for (int j = 0; j < TN; j++)
                    acc[i][j] += regM[i] * regN[j];
        }
        __syncthreads();
    }

    #pragma unroll
    for (int i = 0; i < TM; i++) {
        #pragma unroll
        for (int j = 0; j < TN; j += 4) {
            float4 v;
            v.x = acc[i][j + 0] + bias[cCol + tc + j + 0];
            v.y = acc[i][j + 1] + bias[cCol + tc + j + 1];
            v.z = acc[i][j + 2] + bias[cCol + tc + j + 2];
            v.w = acc[i][j + 3] + bias[cCol + tc + j + 3];
            *reinterpret_cast<float4*>(C + (long)(cRow + tr + i) * N + cCol + tc + j) = v;
        }
    }
}

// ---------------------------------------------------------------------------
// Flash attention (fp32, causal). One thread per query row.
// Block = 128 threads = 128 consecutive query rows of one (b,h).
// K/V staged in smem 32 keys at a time; online softmax; causal tiles skipped.
// qkv layout: row r = b*SEQ+s, cols [0,E)=Q, [E,2E)=K, [2E,3E)=V, head h at h*64.
// Output: g_attn[(b*SEQ+s)*E + h*64 + d]  (heads already merged).
// ---------------------------------------------------------------------------
__global__ __launch_bounds__(128) void flash_attn_kernel()
{
    const int qtile = blockIdx.x;   // 0..15
    const int h     = blockIdx.y;   // 0..15
    const int b     = blockIdx.z;   // 0..1
    const int tid   = threadIdx.x;  // 0..127
    const int qrow  = qtile * 128 + tid;   // sequence position of this thread's query

    __shared__ float4 Ks[32][16];   // 32 keys x 64 dims
    __shared__ float4 Vs[32][16];

    const long rowbase = (long)(b * SEQ + qrow) * QKV_N;
    const int  hoff    = h * HDIM;

    float4 q[16];
    #pragma unroll
    for (int i = 0; i < 16; i++)
        q[i] = *reinterpret_cast<const float4*>(g_qkv + rowbase + hoff + i * 4);

    float4 o[16];
    #pragma unroll
    for (int i = 0; i < 16; i++) o[i] = make_float4(0.f, 0.f, 0.f, 0.f);
    float m = -INFINITY, l = 0.f;

    const int ntiles = qtile * 4 + 4;   // keys up to qtile*128+127 inclusive, 32 per tile

    for (int kt = 0; kt < ntiles; kt++) {
        // Cooperative load: 32 keys x 16 float4 x {K,V}; 8 float4 per thread.
        #pragma unroll
        for (int it = 0; it < 4; it++) {
            int idx = it * 128 + tid;          // 0..511
            int r = idx >> 4;                  // key row in tile
            int c = idx & 15;                  // float4 column
            long grow = (long)(b * SEQ + kt * 32 + r) * QKV_N + hoff + c * 4;
            Ks[r][c] = *reinterpret_cast<const float4*>(g_qkv + grow + EMB);
            Vs[r][c] = *reinterpret_cast<const float4*>(g_qkv + grow + 2 * EMB);
        }
        __syncthreads();

        float s[32];
        float mtile = -INFINITY;
        #pragma unroll
        for (int j = 0; j < 32; j++) {
            float acc = 0.f;
            #pragma unroll
            for (int c = 0; c < 16; c++) {
                float4 kv = Ks[j][c];
                acc += q[c].x * kv.x + q[c].y * kv.y + q[c].z * kv.z + q[c].w * kv.w;
            }
            s[j] = (kt * 32 + j <= qrow) ? acc * 0.125f : -INFINITY;
            mtile = fmaxf(mtile, s[j]);
        }

        float mnew  = fmaxf(m, mtile);
        float alpha = __expf(m - mnew);   // first tile: exp(-inf - finite) = 0, o is 0 anyway
        l *= alpha;
        #pragma unroll
        for (int i = 0; i < 16; i++) {
            o[i].x *= alpha; o[i].y *= alpha; o[i].z *= alpha; o[i].w *= alpha;
        }
        #pragma unroll
        for (int j = 0; j < 32; j++) {
            float p = __expf(s[j] - mnew);   // masked -> exp(-inf)=0
            l += p;
            #pragma unroll
            for (int c = 0; c < 16; c++) {
                float4 vv = Vs[j][c];
                o[c].x += p * vv.x; o[c].y += p * vv.y;
                o[c].z += p * vv.z; o[c].w += p * vv.w;
            }
        }
        m = mnew;
        __syncthreads();
    }

    const float inv = 1.f / l;
    const long obase = (long)(b * SEQ + qrow) * EMB + hoff;
    #pragma unroll
    for (int i = 0; i < 16; i++) {
        float4 v = o[i];
        v.x *= inv; v.y *= inv; v.z *= inv; v.w *= inv;
        *reinterpret_cast<float4*>(g_attn + obase + i * 4) = v;
    }
}

// ---------------------------------------------------------------------------
// Thin wrappers so every stage reads/writes the __device__ globals by symbol
// (kernel_launch stays launches-only: no runtime API besides <<<>>>).
// ---------------------------------------------------------------------------
__global__ __launch_bounds__(256) void qkv_gemm_caller(
    const float* __restrict__ A, const float* __restrict__ B,
    const float* __restrict__ bias);
__global__ __launch_bounds__(256) void out_gemm_caller(
    const float* __restrict__ B, const float* __restrict__ bias,
    float* __restrict__ C);

// Instead of wrappers-with-device-calls (which would duplicate the whole GEMM),
// pass the global symbols' addresses from device-linked constant context:
// simplest correct approach is a tiny kernel that publishes the addresses.
// But device code may take the address of a __device__ global directly in
// host-launched kernel arguments ONLY via cudaGetSymbolAddress. To stay
// launches-only, we instead specialize the GEMM entry points:

__global__ __launch_bounds__(256) void sgemm_qkv_kernel(
    const float* __restrict__ A, const float* __restrict__ Bw,
    const float* __restrict__ bias)
{
    // C = g_qkv, M=ROWS, N=QKV_N, K=EMB
    constexpr int BM = 128, BN = 128, BK = 8, TM = 8, TN = 8;
    constexpr int N = QKV_N, K = EMB;
    __shared__ float As[BK][BM];
    __shared__ float Bs[BK][BN];

    const int tid  = threadIdx.x;
    const int cRow = blockIdx.y * BM;
    const int cCol = blockIdx.x * BN;

    const int aRow = tid >> 1;
    const int aCol = (tid & 1) * 4;
    const int bRow = tid >> 5;
    const int bCol = (tid & 31) * 4;
    const int tr = (tid >> 4) * TM;
    const int tc = (tid & 15) * TN;

    const float* Aptr = A + (long)cRow * K;
    const float* Bptr = Bw + cCol;

    float acc[TM][TN] = {};

    for (int k0 = 0; k0 < K; k0 += BK) {
        float4 av = *reinterpret_cast<const float4*>(Aptr + (long)aRow * K + k0 + aCol);
        As[aCol + 0][aRow] = av.x;
        As[aCol + 1][aRow] = av.y;
        As[aCol + 2][aRow] = av.z;
        As[aCol + 3][aRow] = av.w;
        *reinterpret_cast<float4*>(&Bs[bRow][bCol]) =
            *reinterpret_cast<const float4*>(Bptr + (long)(k0 + bRow) * N + bCol);
        __syncthreads();

        #pragma unroll
        for (int k = 0; k < BK; k++) {
            float regM[TM], regN[TN];
            *reinterpret_cast<float4*>(&regM[0]) = *reinterpret_cast<float4*>(&As[k][tr]);
            *reinterpret_cast<float4*>(&regM[4]) = *reinterpret_cast<float4*>(&As[k][tr + 4]);
            *reinterpret_cast<float4*>(&regN[0]) = *reinterpret_cast<float4*>(&Bs[k][tc]);
            *reinterpret_cast<float4*>(&regN[4]) = *reinterpret_cast<float4*>(&Bs[k][tc + 4]);
            #pragma unroll
            for (int i = 0; i < TM; i++)
                #pragma unroll
                for (int j = 0; j < TN; j++)
                    acc[i][j] += regM[i] * regN[j];
        }
        __syncthreads();
    }

    #pragma unroll
    for (int i = 0; i < TM; i++) {
        #pragma unroll
        for (int j = 0; j < TN; j += 4) {
            float4 v;
            v.x = acc[i][j + 0] + bias[cCol + tc + j + 0];
            v.y = acc[i][j + 1] + bias[cCol + tc + j + 1];
            v.z = acc[i][j + 2] + bias[cCol + tc + j + 2];
            v.w = acc[i][j + 3] + bias[cCol + tc + j + 3];
            *reinterpret_cast<float4*>(g_qkv + (long)(cRow + tr + i) * N + cCol + tc + j) = v;
        }
    }
}

__global__ __launch_bounds__(256) void sgemm_proj_kernel(
    const float* __restrict__ Bw, const float* __restrict__ bias,
    float* __restrict__ C)
{
    // A = g_attn, M=ROWS, N=EMB, K=EMB
    constexpr int BM = 128, BN = 128, BK = 8, TM = 8, TN = 8;
    constexpr int N = EMB, K = EMB;
    __shared__ float As[BK][BM];
    __shared__ float Bs[BK][BN];

    const int tid  = threadIdx.x;
    const int cRow = blockIdx.y * BM;
    const int cCol = blockIdx.x * BN;

    const int aRow = tid >> 1;
    const int aCol = (tid & 1) * 4;
    const int bRow = tid >> 5;
    const int bCol = (tid & 31) * 4;
    const int tr = (tid >> 4) * TM;
    const int tc = (tid & 15) * TN;

    const float* Aptr = g_attn + (long)cRow * K;
    const float* Bptr = Bw + cCol;

    float acc[TM][TN] = {};

    for (int k0 = 0; k0 < K; k0 += BK) {
        float4 av = *reinterpret_cast<const float4*>(Aptr + (long)aRow * K + k0 + aCol);
        As[aCol + 0][aRow] = av.x;
        As[aCol + 1][aRow] = av.y;
        As[aCol + 2][aRow] = av.z;
        As[aCol + 3][aRow] = av.w;
        *reinterpret_cast<float4*>(&Bs[bRow][bCol]) =
            *reinterpret_cast<const float4*>(Bptr + (long)(k0 + bRow) * N + bCol);
        __syncthreads();

        #pragma unroll
        for (int k = 0; k < BK; k++) {
            float regM[TM], regN[TN];
            *reinterpret_cast<float4*>(&regM[0]) = *reinterpret_cast<float4*>(&As[k][tr]);
            *reinterpret_cast<float4*>(&regM[4]) = *reinterpret_cast<float4*>(&As[k][tr + 4]);
            *reinterpret_cast<float4*>(&regN[0]) = *reinterpret_cast<float4*>(&Bs[k][tc]);
            *reinterpret_cast<float4*>(&regN[4]) = *reinterpret_cast<float4*>(&Bs[k][tc + 4]);
            #pragma unroll
            for (int i = 0; i < TM; i++)
                #pragma unroll
                for (int j = 0; j < TN; j++)
                    acc[i][j] += regM[i] * regN[j];
        }
        __syncthreads();
    }

    #pragma unroll
    for (int i = 0; i < TM; i++) {
        #pragma unroll
        for (int j = 0; j < TN; j += 4) {
            float4 v;
            v.x = acc[i][j + 0] + bias[cCol + tc + j + 0];
            v.y = acc[i][j + 1] + bias[cCol + tc + j + 1];
            v.z = acc[i][j + 2] + bias[cCol + tc + j + 2];
            v.w = acc[i][j + 3] + bias[cCol + tc + j + 3];
            *reinterpret_cast<float4*>(C + (long)(cRow + tr + i) * N + cCol + tc + j) = v;
        }
    }
}

// ---------------------------------------------------------------------------
// Launch: three kernel launches, nothing else.
// ---------------------------------------------------------------------------
extern "C" void kernel_launch(void* const* d_in, const int* in_sizes, int n_in,
                              void* d_out, int out_size)
{
    const float* hidden = (const float*)d_in[0];
    const float* w_attn = (const float*)d_in[1];
    const float* b_attn = (const float*)d_in[2];
    const float* w_proj = (const float*)d_in[3];
    const float* b_proj = (const float*)d_in[4];
    float* out = (float*)d_out;

    // 1) QKV projection: [4096,1024] @ [1024,3072] + bias -> g_qkv
    sgemm_qkv_kernel<<<dim3(QKV_N / 128, ROWS / 128), 256>>>(hidden, w_attn, b_attn);

    // 2) Causal multi-head flash attention: g_qkv -> g_attn (merged heads)
    flash_attn_kernel<<<dim3(SEQ / 128, HEADS, BATCH), 128>>>();

    // 3) Output projection: g_attn @ [1024,1024] + bias -> out
    sgemm_proj_kernel<<<dim3(EMB / 128, ROWS / 128), 256>>>(w_proj, b_proj, out);
}

// round 3
// speedup vs baseline: 1.4102x; 1.4102x over previous
#include <cuda_runtime.h>
#include <math.h>
#include <stdint.h>

// ---------------------------------------------------------------------------
// Problem constants: B=2, S=2048, E=1024, H=16, D=64
// ---------------------------------------------------------------------------
#define BATCH 2
#define SEQ   2048
#define EMB   1024
#define HEADS 16
#define HDIM  64
#define ROWS  (BATCH * SEQ)        // 4096
#define QKV_N (3 * EMB)            // 3072

// Scratch (allocation-free rule: __device__ globals)
__device__ float g_qkv[ROWS * QKV_N];   // 48 MB
__device__ float g_attn[ROWS * EMB];    // 16 MB

// ---------------------------------------------------------------------------
// tf32 helpers
// ---------------------------------------------------------------------------
__device__ __forceinline__ uint32_t f32_to_tf32(float x) {
    uint32_t r;
    asm("cvt.rna.tf32.f32 %0, %1;" : "=r"(r) : "f"(x));
    return r;
}

__device__ __forceinline__ void mma_tf32_16x8x8(
    float& c0, float& c1, float& c2, float& c3,
    uint32_t a0, uint32_t a1, uint32_t a2, uint32_t a3,
    uint32_t b0, uint32_t b1)
{
    asm volatile(
        "mma.sync.aligned.m16n8k8.row.col.f32.tf32.tf32.f32 "
        "{%0,%1,%2,%3}, {%4,%5,%6,%7}, {%8,%9}, {%0,%1,%2,%3};"
        : "+f"(c0), "+f"(c1), "+f"(c2), "+f"(c3)
        : "r"(a0), "r"(a1), "r"(a2), "r"(a3), "r"(b0), "r"(b1));
}

// ---------------------------------------------------------------------------
// tf32 tensor-core GEMM with fused bias: C[M,N] = A[M,K] @ B[K,N] + bias[N]
// BM=BN=128, BK=32, 256 threads (8 warps, 2x4), warp tile 64x32 (4x4 atoms
// of m16n8k8). A smem stride 36, B smem stride 136 => conflict-free frags.
// ---------------------------------------------------------------------------
template<int N, int K>
__device__ __forceinline__ void gemm_tf32(
    const float* __restrict__ A, const float* __restrict__ Bw,
    const float* __restrict__ bias, float* __restrict__ C)
{
    constexpr int BM = 128, BN = 128, BK = 32;
    constexpr int AS = BK + 4;    // 36 floats: frag bank = (4g+t)%32, unique
    constexpr int BS = BN + 8;    // 136 floats: frag bank = (8t+g)%32, unique

    __shared__ uint32_t As[BM * AS];
    __shared__ uint32_t Bs[BK * BS];

    const int tid    = threadIdx.x;
    const int lane   = tid & 31;
    const int wid    = tid >> 5;
    const int warp_m = wid >> 2;           // 0..1 -> rows 64*warp_m
    const int warp_n = wid & 3;            // 0..3 -> cols 32*warp_n
    const int g      = lane >> 2;          // 0..7
    const int t      = lane & 3;           // 0..3

    const int cRow = blockIdx.y * BM;
    const int cCol = blockIdx.x * BN;

    float acc[4][4][4];
    #pragma unroll
    for (int i = 0; i < 4; i++)
        #pragma unroll
        for (int j = 0; j < 4; j++)
            #pragma unroll
            for (int r = 0; r < 4; r++) acc[i][j][r] = 0.f;

    for (int k0 = 0; k0 < K; k0 += BK) {
        // --- fill A tile: 128x32 floats = 1024 float4, 4 per thread ---
        #pragma unroll
        for (int i = 0; i < 4; i++) {
            int idx = i * 256 + tid;
            int m   = idx >> 3;            // 0..127
            int c4  = (idx & 7) * 4;       // 0,4,...,28
            float4 v = *reinterpret_cast<const float4*>(
                A + (long)(cRow + m) * K + k0 + c4);
            As[m * AS + c4 + 0] = f32_to_tf32(v.x);
            As[m * AS + c4 + 1] = f32_to_tf32(v.y);
            As[m * AS + c4 + 2] = f32_to_tf32(v.z);
            As[m * AS + c4 + 3] = f32_to_tf32(v.w);
        }
        // --- fill B tile: 32x128 floats = 1024 float4, 4 per thread ---
        #pragma unroll
        for (int i = 0; i < 4; i++) {
            int idx = i * 256 + tid;
            int kr  = idx >> 5;            // 0..31
            int nc  = (idx & 31) * 4;      // 0..124
            float4 v = *reinterpret_cast<const float4*>(
                Bw + (long)(k0 + kr) * N + cCol + nc);
            Bs[kr * BS + nc + 0] = f32_to_tf32(v.x);
            Bs[kr * BS + nc + 1] = f32_to_tf32(v.y);
            Bs[kr * BS + nc + 2] = f32_to_tf32(v.z);
            Bs[kr * BS + nc + 3] = f32_to_tf32(v.w);
        }
        __syncthreads();

        #pragma unroll
        for (int kk = 0; kk < 4; kk++) {
            const int k8 = kk * 8;
            uint32_t a[4][4];
            #pragma unroll
            for (int ma = 0; ma < 4; ma++) {
                int row = warp_m * 64 + ma * 16;
                a[ma][0] = As[(row + g) * AS + k8 + t];
                a[ma][1] = As[(row + g + 8) * AS + k8 + t];
                a[ma][2] = As[(row + g) * AS + k8 + t + 4];
                a[ma][3] = As[(row + g + 8) * AS + k8 + t + 4];
            }
            uint32_t b[4][2];
            #pragma unroll
            for (int na = 0; na < 4; na++) {
                int col = warp_n * 32 + na * 8 + g;
                b[na][0] = Bs[(k8 + t) * BS + col];
                b[na][1] = Bs[(k8 + t + 4) * BS + col];
            }
            #pragma unroll
            for (int ma = 0; ma < 4; ma++)
                #pragma unroll
                for (int na = 0; na < 4; na++)
                    mma_tf32_16x8x8(acc[ma][na][0], acc[ma][na][1],
                                    acc[ma][na][2], acc[ma][na][3],
                                    a[ma][0], a[ma][1], a[ma][2], a[ma][3],
                                    b[na][0], b[na][1]);
        }
        __syncthreads();
    }

    // --- epilogue: fused bias, float2 stores ---
    #pragma unroll
    for (int ma = 0; ma < 4; ma++) {
        #pragma unroll
        for (int na = 0; na < 4; na++) {
            int row = cRow + warp_m * 64 + ma * 16 + g;
            int col = cCol + warp_n * 32 + na * 8 + 2 * t;
            float2 bv = *reinterpret_cast<const float2*>(bias + col);
            float2 v0, v1;
            v0.x = acc[ma][na][0] + bv.x;
            v0.y = acc[ma][na][1] + bv.y;
            v1.x = acc[ma][na][2] + bv.x;
            v1.y = acc[ma][na][3] + bv.y;
            *reinterpret_cast<float2*>(C + (long)row * N + col)       = v0;
            *reinterpret_cast<float2*>(C + (long)(row + 8) * N + col) = v1;
        }
    }
}

__global__ __launch_bounds__(256) void qkv_tf32_kernel(
    const float* __restrict__ A, const float* __restrict__ Bw,
    const float* __restrict__ bias)
{
    gemm_tf32<QKV_N, EMB>(A, Bw, bias, g_qkv);
}

__global__ __launch_bounds__(256) void proj_tf32_kernel(
    const float* __restrict__ Bw, const float* __restrict__ bias,
    float* __restrict__ C)
{
    gemm_tf32<EMB, EMB>(g_attn, Bw, bias, C);
}

// ---------------------------------------------------------------------------
// Flash attention (fp32, causal). One thread per query row. Unchanged from
// the passing R2 kernel (attention is next round's target).
// ---------------------------------------------------------------------------
__global__ __launch_bounds__(128) void flash_attn_kernel()
{
    const int qtile = blockIdx.x;   // 0..15
    const int h     = blockIdx.y;   // 0..15
    const int b     = blockIdx.z;   // 0..1
    const int tid   = threadIdx.x;  // 0..127
    const int qrow  = qtile * 128 + tid;

    __shared__ float4 Ks[32][16];   // 32 keys x 64 dims
    __shared__ float4 Vs[32][16];

    const long rowbase = (long)(b * SEQ + qrow) * QKV_N;
    const int  hoff    = h * HDIM;

    float4 q[16];
    #pragma unroll
    for (int i = 0; i < 16; i++)
        q[i] = *reinterpret_cast<const float4*>(g_qkv + rowbase + hoff + i * 4);

    float4 o[16];
    #pragma unroll
    for (int i = 0; i < 16; i++) o[i] = make_float4(0.f, 0.f, 0.f, 0.f);
    float m = -INFINITY, l = 0.f;

    const int ntiles = qtile * 4 + 4;

    for (int kt = 0; kt < ntiles; kt++) {
        #pragma unroll
        for (int it = 0; it < 4; it++) {
            int idx = it * 128 + tid;
            int r = idx >> 4;
            int c = idx & 15;
            long grow = (long)(b * SEQ + kt * 32 + r) * QKV_N + hoff + c * 4;
            Ks[r][c] = *reinterpret_cast<const float4*>(g_qkv + grow + EMB);
            Vs[r][c] = *reinterpret_cast<const float4*>(g_qkv + grow + 2 * EMB);
        }
        __syncthreads();

        float s[32];
        float mtile = -INFINITY;
        #pragma unroll
        for (int j = 0; j < 32; j++) {
            float acc = 0.f;
            #pragma unroll
            for (int c = 0; c < 16; c++) {
                float4 kv = Ks[j][c];
                acc += q[c].x * kv.x + q[c].y * kv.y + q[c].z * kv.z + q[c].w * kv.w;
            }
            s[j] = (kt * 32 + j <= qrow) ? acc * 0.125f : -INFINITY;
            mtile = fmaxf(mtile, s[j]);
        }

        float mnew  = fmaxf(m, mtile);
        float alpha = __expf(m - mnew);
        l *= alpha;
        #pragma unroll
        for (int i = 0; i < 16; i++) {
            o[i].x *= alpha; o[i].y *= alpha; o[i].z *= alpha; o[i].w *= alpha;
        }
        #pragma unroll
        for (int j = 0; j < 32; j++) {
            float p = __expf(s[j] - mnew);
            l += p;
            #pragma unroll
            for (int c = 0; c < 16; c++) {
                float4 vv = Vs[j][c];
                o[c].x += p * vv.x; o[c].y += p * vv.y;
                o[c].z += p * vv.z; o[c].w += p * vv.w;
            }
        }
        m = mnew;
        __syncthreads();
    }

    const float inv = 1.f / l;
    const long obase = (long)(b * SEQ + qrow) * EMB + hoff;
    #pragma unroll
    for (int i = 0; i < 16; i++) {
        float4 v = o[i];
        v.x *= inv; v.y *= inv; v.z *= inv; v.w *= inv;
        *reinterpret_cast<float4*>(g_attn + obase + i * 4) = v;
    }
}

// ---------------------------------------------------------------------------
// Launch: three kernel launches, nothing else.
// ---------------------------------------------------------------------------
extern "C" void kernel_launch(void* const* d_in, const int* in_sizes, int n_in,
                              void* d_out, int out_size)
{
    const float* hidden = (const float*)d_in[0];
    const float* w_attn = (const float*)d_in[1];
    const float* b_attn = (const float*)d_in[2];
    const float* w_proj = (const float*)d_in[3];
    const float* b_proj = (const float*)d_in[4];
    float* out = (float*)d_out;

    // 1) QKV projection: [4096,1024] @ [1024,3072] + bias -> g_qkv (tf32 TC)
    qkv_tf32_kernel<<<dim3(QKV_N / 128, ROWS / 128), 256>>>(hidden, w_attn, b_attn);

    // 2) Causal multi-head flash attention: g_qkv -> g_attn (merged heads)
    flash_attn_kernel<<<dim3(SEQ / 128, HEADS, BATCH), 128>>>();

    // 3) Output projection: g_attn @ [1024,1024] + bias -> out (tf32 TC)
    proj_tf32_kernel<<<dim3(EMB / 128, ROWS / 128), 256>>>(w_proj, b_proj, out);
}

// round 5
// speedup vs baseline: 2.9684x; 2.1050x over previous
#include <cuda_runtime.h>
#include <math.h>
#include <stdint.h>

// ---------------------------------------------------------------------------
// Problem constants: B=2, S=2048, E=1024, H=16, D=64
// ---------------------------------------------------------------------------
#define BATCH 2
#define SEQ   2048
#define EMB   1024
#define HEADS 16
#define HDIM  64
#define ROWS  (BATCH * SEQ)        // 4096
#define QKV_N (3 * EMB)            // 3072

// Scratch (allocation-free rule: __device__ globals)
__device__ float g_qkv[ROWS * QKV_N];   // 48 MB
__device__ float g_attn[ROWS * EMB];    // 16 MB

// ---------------------------------------------------------------------------
// tf32 helpers
// ---------------------------------------------------------------------------
__device__ __forceinline__ uint32_t f32_to_tf32(float x) {
    uint32_t r;
    asm("cvt.rna.tf32.f32 %0, %1;" : "=r"(r) : "f"(x));
    return r;
}

// x ~= hi + lo, both tf32-representable (fp32 bit patterns)
__device__ __forceinline__ void split_tf32(float x, uint32_t& hi, uint32_t& lo) {
    uint32_t h;
    asm("cvt.rna.tf32.f32 %0, %1;" : "=r"(h) : "f"(x));
    float r = x - __uint_as_float(h);
    uint32_t l;
    asm("cvt.rna.tf32.f32 %0, %1;" : "=r"(l) : "f"(r));
    hi = h; lo = l;
}

__device__ __forceinline__ void mma_tf32_16x8x8(
    float& c0, float& c1, float& c2, float& c3,
    uint32_t a0, uint32_t a1, uint32_t a2, uint32_t a3,
    uint32_t b0, uint32_t b1)
{
    asm volatile(
        "mma.sync.aligned.m16n8k8.row.col.f32.tf32.tf32.f32 "
        "{%0,%1,%2,%3}, {%4,%5,%6,%7}, {%8,%9}, {%0,%1,%2,%3};"
        : "+f"(c0), "+f"(c1), "+f"(c2), "+f"(c3)
        : "r"(a0), "r"(a1), "r"(a2), "r"(a3), "r"(b0), "r"(b1));
}

// ---------------------------------------------------------------------------
// tf32 tensor-core GEMM with fused bias (unchanged from R3, passing)
// ---------------------------------------------------------------------------
template<int N, int K>
__device__ __forceinline__ void gemm_tf32(
    const float* __restrict__ A, const float* __restrict__ Bw,
    const float* __restrict__ bias, float* __restrict__ C)
{
    constexpr int BM = 128, BN = 128, BK = 32;
    constexpr int AS = BK + 4;
    constexpr int BS = BN + 8;

    __shared__ uint32_t As[BM * AS];
    __shared__ uint32_t Bs[BK * BS];

    const int tid    = threadIdx.x;
    const int lane   = tid & 31;
    const int wid    = tid >> 5;
    const int warp_m = wid >> 2;
    const int warp_n = wid & 3;
    const int g      = lane >> 2;
    const int t      = lane & 3;

    const int cRow = blockIdx.y * BM;
    const int cCol = blockIdx.x * BN;

    float acc[4][4][4];
    #pragma unroll
    for (int i = 0; i < 4; i++)
        #pragma unroll
        for (int j = 0; j < 4; j++)
            #pragma unroll
            for (int r = 0; r < 4; r++) acc[i][j][r] = 0.f;

    for (int k0 = 0; k0 < K; k0 += BK) {
        #pragma unroll
        for (int i = 0; i < 4; i++) {
            int idx = i * 256 + tid;
            int m   = idx >> 3;
            int c4  = (idx & 7) * 4;
            float4 v = *reinterpret_cast<const float4*>(
                A + (long)(cRow + m) * K + k0 + c4);
            As[m * AS + c4 + 0] = f32_to_tf32(v.x);
            As[m * AS + c4 + 1] = f32_to_tf32(v.y);
            As[m * AS + c4 + 2] = f32_to_tf32(v.z);
            As[m * AS + c4 + 3] = f32_to_tf32(v.w);
        }
        #pragma unroll
        for (int i = 0; i < 4; i++) {
            int idx = i * 256 + tid;
            int kr  = idx >> 5;
            int nc  = (idx & 31) * 4;
            float4 v = *reinterpret_cast<const float4*>(
                Bw + (long)(k0 + kr) * N + cCol + nc);
            Bs[kr * BS + nc + 0] = f32_to_tf32(v.x);
            Bs[kr * BS + nc + 1] = f32_to_tf32(v.y);
            Bs[kr * BS + nc + 2] = f32_to_tf32(v.z);
            Bs[kr * BS + nc + 3] = f32_to_tf32(v.w);
        }
        __syncthreads();

        #pragma unroll
        for (int kk = 0; kk < 4; kk++) {
            const int k8 = kk * 8;
            uint32_t a[4][4];
            #pragma unroll
            for (int ma = 0; ma < 4; ma++) {
                int row = warp_m * 64 + ma * 16;
                a[ma][0] = As[(row + g) * AS + k8 + t];
                a[ma][1] = As[(row + g + 8) * AS + k8 + t];
                a[ma][2] = As[(row + g) * AS + k8 + t + 4];
                a[ma][3] = As[(row + g + 8) * AS + k8 + t + 4];
            }
            uint32_t b[4][2];
            #pragma unroll
            for (int na = 0; na < 4; na++) {
                int col = warp_n * 32 + na * 8 + g;
                b[na][0] = Bs[(k8 + t) * BS + col];
                b[na][1] = Bs[(k8 + t + 4) * BS + col];
            }
            #pragma unroll
            for (int ma = 0; ma < 4; ma++)
                #pragma unroll
                for (int na = 0; na < 4; na++)
                    mma_tf32_16x8x8(acc[ma][na][0], acc[ma][na][1],
                                    acc[ma][na][2], acc[ma][na][3],
                                    a[ma][0], a[ma][1], a[ma][2], a[ma][3],
                                    b[na][0], b[na][1]);
        }
        __syncthreads();
    }

    #pragma unroll
    for (int ma = 0; ma < 4; ma++) {
        #pragma unroll
        for (int na = 0; na < 4; na++) {
            int row = cRow + warp_m * 64 + ma * 16 + g;
            int col = cCol + warp_n * 32 + na * 8 + 2 * t;
            float2 bv = *reinterpret_cast<const float2*>(bias + col);
            float2 v0, v1;
            v0.x = acc[ma][na][0] + bv.x;
            v0.y = acc[ma][na][1] + bv.y;
            v1.x = acc[ma][na][2] + bv.x;
            v1.y = acc[ma][na][3] + bv.y;
            *reinterpret_cast<float2*>(C + (long)row * N + col)       = v0;
            *reinterpret_cast<float2*>(C + (long)(row + 8) * N + col) = v1;
        }
    }
}

__global__ __launch_bounds__(256) void qkv_tf32_kernel(
    const float* __restrict__ A, const float* __restrict__ Bw,
    const float* __restrict__ bias)
{
    gemm_tf32<QKV_N, EMB>(A, Bw, bias, g_qkv);
}

__global__ __launch_bounds__(256) void proj_tf32_kernel(
    const float* __restrict__ Bw, const float* __restrict__ bias,
    float* __restrict__ C)
{
    gemm_tf32<EMB, EMB>(g_attn, Bw, bias, C);
}

// ---------------------------------------------------------------------------
// Flash attention with tf32 tensor cores.
// Block: 256 threads (8 warps) = 128 query rows of one (b,h). Warp w owns
// rows [16w,16w+16). K/V tiles of 64 keys in smem.
//   K: raw fp32, stride 68 (bank (4g+t)%32, conflict-free); big/small tf32
//      split computed at fragment-load time.
//   V: tf32-rounded, stride 72 (bank (8t+g)%32, conflict-free).
// Online softmax in C-frag layout; P reshaped C->A frag via quad shuffles.
// Precision: QK^T 3-term split (~fp32 logits); PV: P split exact, V tf32.
// ---------------------------------------------------------------------------
#define KS_STRIDE 68
#define VS_STRIDE 72

__global__ __launch_bounds__(256) void flash_attn_mma_kernel()
{
    const int qt   = (int)gridDim.x - 1 - (int)blockIdx.x;  // heavy blocks first
    const int h    = blockIdx.y;
    const int b    = blockIdx.z;
    const int tid  = threadIdx.x;
    const int lane = tid & 31;
    const int w    = tid >> 5;
    const int g    = lane >> 2;   // 0..7
    const int t    = lane & 3;    // 0..3

    const int qbase = qt * 128;
    const int row0  = qbase + w * 16 + g;   // this thread's rows: row0, row0+8
    const int hoff  = h * HDIM;

    __shared__ float Ks[64 * KS_STRIDE];   // raw fp32 K tile   (17408 B)
    __shared__ float Vs[64 * VS_STRIDE];   // tf32 V tile       (18432 B)

    // ---- Q fragments (scaled by 1/sqrt(D)=0.125, split big/small) ----
    uint32_t qb[8][4], qs[8][4];
    {
        const long r0 = (long)(b * SEQ + row0) * QKV_N + hoff;
        const long r1 = r0 + 8L * QKV_N;
        #pragma unroll
        for (int ka = 0; ka < 8; ka++) {
            int c0 = ka * 8 + t, c1 = c0 + 4;
            split_tf32(g_qkv[r0 + c0] * 0.125f, qb[ka][0], qs[ka][0]);
            split_tf32(g_qkv[r1 + c0] * 0.125f, qb[ka][1], qs[ka][1]);
            split_tf32(g_qkv[r0 + c1] * 0.125f, qb[ka][2], qs[ka][2]);
            split_tf32(g_qkv[r1 + c1] * 0.125f, qb[ka][3], qs[ka][3]);
        }
    }

    float o[8][4];
    #pragma unroll
    for (int na = 0; na < 8; na++)
        #pragma unroll
        for (int e = 0; e < 4; e++) o[na][e] = 0.f;
    float m0 = -INFINITY, m1 = -INFINITY, l0 = 0.f, l1 = 0.f;

    const int ntiles = 2 * qt + 2;
    for (int kt = 0; kt < ntiles; kt++) {
        // ---- cooperative K/V tile load (K raw; V tf32-rounded) ----
        #pragma unroll
        for (int i = 0; i < 4; i++) {
            int idx = i * 256 + tid;
            int j   = idx >> 4;            // key row 0..63
            int c4  = (idx & 15) * 4;      // dim 0..60
            long base = (long)(b * SEQ + kt * 64 + j) * QKV_N + hoff + c4;
            float4 kv = *reinterpret_cast<const float4*>(g_qkv + base + EMB);
            float4 vv = *reinterpret_cast<const float4*>(g_qkv + base + 2 * EMB);
            *reinterpret_cast<float4*>(&Ks[j * KS_STRIDE + c4]) = kv;
            float4 vt;
            vt.x = __uint_as_float(f32_to_tf32(vv.x));
            vt.y = __uint_as_float(f32_to_tf32(vv.y));
            vt.z = __uint_as_float(f32_to_tf32(vv.z));
            vt.w = __uint_as_float(f32_to_tf32(vv.w));
            *reinterpret_cast<float4*>(&Vs[j * VS_STRIDE + c4]) = vt;
        }
        __syncthreads();

        // ---- scores S = Q K^T (3-term split tf32) ----
        float s[8][4];
        #pragma unroll
        for (int na = 0; na < 8; na++)
            #pragma unroll
            for (int e = 0; e < 4; e++) s[na][e] = 0.f;

        #pragma unroll
        for (int ka = 0; ka < 8; ka++) {
            #pragma unroll
            for (int na = 0; na < 8; na++) {
                float k0 = Ks[(na * 8 + g) * KS_STRIDE + ka * 8 + t];
                float k1 = Ks[(na * 8 + g) * KS_STRIDE + ka * 8 + t + 4];
                uint32_t bb0, bl0, bb1, bl1;
                split_tf32(k0, bb0, bl0);
                split_tf32(k1, bb1, bl1);
                mma_tf32_16x8x8(s[na][0], s[na][1], s[na][2], s[na][3],
                                qb[ka][0], qb[ka][1], qb[ka][2], qb[ka][3], bb0, bb1);
                mma_tf32_16x8x8(s[na][0], s[na][1], s[na][2], s[na][3],
                                qs[ka][0], qs[ka][1], qs[ka][2], qs[ka][3], bb0, bb1);
                mma_tf32_16x8x8(s[na][0], s[na][1], s[na][2], s[na][3],
                                qb[ka][0], qb[ka][1], qb[ka][2], qb[ka][3], bl0, bl1);
            }
        }

        // ---- causal mask (diagonal tiles only) ----
        if (kt >= 2 * qt) {
            const int colbase = kt * 64 + 2 * t;
            #pragma unroll
            for (int na = 0; na < 8; na++) {
                int c = colbase + 8 * na;
                if (c     > row0)     s[na][0] = -INFINITY;
                if (c + 1 > row0)     s[na][1] = -INFINITY;
                if (c     > row0 + 8) s[na][2] = -INFINITY;
                if (c + 1 > row0 + 8) s[na][3] = -INFINITY;
            }
        }

        // ---- online softmax (rows row0, row0+8) ----
        float tm0 = -INFINITY, tm1 = -INFINITY;
        #pragma unroll
        for (int na = 0; na < 8; na++) {
            tm0 = fmaxf(tm0, fmaxf(s[na][0], s[na][1]));
            tm1 = fmaxf(tm1, fmaxf(s[na][2], s[na][3]));
        }
        tm0 = fmaxf(tm0, __shfl_xor_sync(0xffffffffu, tm0, 1));
        tm0 = fmaxf(tm0, __shfl_xor_sync(0xffffffffu, tm0, 2));
        tm1 = fmaxf(tm1, __shfl_xor_sync(0xffffffffu, tm1, 1));
        tm1 = fmaxf(tm1, __shfl_xor_sync(0xffffffffu, tm1, 2));

        float mn0 = fmaxf(m0, tm0), mn1 = fmaxf(m1, tm1);
        float a0 = __expf(m0 - mn0), a1 = __expf(m1 - mn1);
        l0 *= a0; l1 *= a1;
        #pragma unroll
        for (int na = 0; na < 8; na++) {
            o[na][0] *= a0; o[na][1] *= a0;
            o[na][2] *= a1; o[na][3] *= a1;
        }

        float rs0 = 0.f, rs1 = 0.f;
        #pragma unroll
        for (int na = 0; na < 8; na++) {
            s[na][0] = __expf(s[na][0] - mn0);
            s[na][1] = __expf(s[na][1] - mn0);
            s[na][2] = __expf(s[na][2] - mn1);
            s[na][3] = __expf(s[na][3] - mn1);
            rs0 += s[na][0] + s[na][1];
            rs1 += s[na][2] + s[na][3];
        }
        rs0 += __shfl_xor_sync(0xffffffffu, rs0, 1);
        rs0 += __shfl_xor_sync(0xffffffffu, rs0, 2);
        rs1 += __shfl_xor_sync(0xffffffffu, rs1, 1);
        rs1 += __shfl_xor_sync(0xffffffffu, rs1, 2);
        l0 += rs0; l1 += rs1;
        m0 = mn0; m1 = mn1;

        // ---- O += P V  (P: C-frag -> A-frag via quad shuffles, split) ----
        const unsigned src0 = (lane & 28u) | ((unsigned)t >> 1);
        const unsigned src1 = src0 + 2;
        const bool odd = (t & 1);
        #pragma unroll
        for (int ka = 0; ka < 8; ka++) {
            float e0 = __shfl_sync(0xffffffffu, s[ka][0], src0);
            float e1 = __shfl_sync(0xffffffffu, s[ka][1], src0);
            float e2 = __shfl_sync(0xffffffffu, s[ka][2], src0);
            float e3 = __shfl_sync(0xffffffffu, s[ka][3], src0);
            float f0 = __shfl_sync(0xffffffffu, s[ka][0], src1);
            float f1 = __shfl_sync(0xffffffffu, s[ka][1], src1);
            float f2 = __shfl_sync(0xffffffffu, s[ka][2], src1);
            float f3 = __shfl_sync(0xffffffffu, s[ka][3], src1);
            float pa0 = odd ? e1 : e0;   // P[g][ka*8+t]
            float pa1 = odd ? e3 : e2;   // P[g+8][ka*8+t]
            float pa2 = odd ? f1 : f0;   // P[g][ka*8+t+4]
            float pa3 = odd ? f3 : f2;   // P[g+8][ka*8+t+4]
            uint32_t pb[4], pl[4];
            split_tf32(pa0, pb[0], pl[0]);
            split_tf32(pa1, pb[1], pl[1]);
            split_tf32(pa2, pb[2], pl[2]);
            split_tf32(pa3, pb[3], pl[3]);
            #pragma unroll
            for (int na = 0; na < 8; na++) {
                uint32_t v0 = __float_as_uint(Vs[(ka * 8 + t) * VS_STRIDE + na * 8 + g]);
                uint32_t v1 = __float_as_uint(Vs[(ka * 8 + t + 4) * VS_STRIDE + na * 8 + g]);
                mma_tf32_16x8x8(o[na][0], o[na][1], o[na][2], o[na][3],
                                pb[0], pb[1], pb[2], pb[3], v0, v1);
                mma_tf32_16x8x8(o[na][0], o[na][1], o[na][2], o[na][3],
                                pl[0], pl[1], pl[2], pl[3], v0, v1);
            }
        }
        __syncthreads();   // protect K/V tiles before next iteration's fill
    }

    // ---- epilogue: normalize and store merged-head output ----
    const float inv0 = 1.f / l0, inv1 = 1.f / l1;
    const long ob0 = (long)(b * SEQ + row0) * EMB + hoff;
    const long ob1 = ob0 + 8L * EMB;
    #pragma unroll
    for (int na = 0; na < 8; na++) {
        int col = na * 8 + 2 * t;
        float2 w0 = make_float2(o[na][0] * inv0, o[na][1] * inv0);
        float2 w1 = make_float2(o[na][2] * inv1, o[na][3] * inv1);
        *reinterpret_cast<float2*>(g_attn + ob0 + col) = w0;
        *reinterpret_cast<float2*>(g_attn + ob1 + col) = w1;
    }
}

// ---------------------------------------------------------------------------
// Launch: three kernel launches, nothing else.
// ---------------------------------------------------------------------------
extern "C" void kernel_launch(void* const* d_in, const int* in_sizes, int n_in,
                              void* d_out, int out_size)
{
    const float* hidden = (const float*)d_in[0];
    const float* w_attn = (const float*)d_in[1];
    const float* b_attn = (const float*)d_in[2];
    const float* w_proj = (const float*)d_in[3];
    const float* b_proj = (const float*)d_in[4];
    float* out = (float*)d_out;

    // 1) QKV projection (tf32 TC): [4096,1024] @ [1024,3072] + bias -> g_qkv
    qkv_tf32_kernel<<<dim3(QKV_N / 128, ROWS / 128), 256>>>(hidden, w_attn, b_attn);

    // 2) Causal MHA, tf32 MMA flash attention: g_qkv -> g_attn (merged heads)
    flash_attn_mma_kernel<<<dim3(SEQ / 128, HEADS, BATCH), 256>>>();

    // 3) Output projection (tf32 TC): g_attn @ [1024,1024] + bias -> out
    proj_tf32_kernel<<<dim3(EMB / 128, ROWS / 128), 256>>>(w_proj, b_proj, out);
}

// round 6
// speedup vs baseline: 3.3940x; 1.1434x over previous
#include <cuda_runtime.h>
#include <cuda_bf16.h>
#include <math.h>
#include <stdint.h>

// ---------------------------------------------------------------------------
// Problem constants: B=2, S=2048, E=1024, H=16, D=64
// ---------------------------------------------------------------------------
#define BATCH 2
#define SEQ   2048
#define EMB   1024
#define HEADS 16
#define HDIM  64
#define ROWS  (BATCH * SEQ)        // 4096
#define QKV_N (3 * EMB)            // 3072

// Scratch (allocation-free rule: __device__ globals)
__device__ float g_qkv[ROWS * QKV_N];   // 48 MB
__device__ float g_attn[ROWS * EMB];    // 16 MB

// ---------------------------------------------------------------------------
// tf32 helpers (GEMMs, unchanged from R5 passing kernel)
// ---------------------------------------------------------------------------
__device__ __forceinline__ uint32_t f32_to_tf32(float x) {
    uint32_t r;
    asm("cvt.rna.tf32.f32 %0, %1;" : "=r"(r) : "f"(x));
    return r;
}

__device__ __forceinline__ void mma_tf32_16x8x8(
    float& c0, float& c1, float& c2, float& c3,
    uint32_t a0, uint32_t a1, uint32_t a2, uint32_t a3,
    uint32_t b0, uint32_t b1)
{
    asm volatile(
        "mma.sync.aligned.m16n8k8.row.col.f32.tf32.tf32.f32 "
        "{%0,%1,%2,%3}, {%4,%5,%6,%7}, {%8,%9}, {%0,%1,%2,%3};"
        : "+f"(c0), "+f"(c1), "+f"(c2), "+f"(c3)
        : "r"(a0), "r"(a1), "r"(a2), "r"(a3), "r"(b0), "r"(b1));
}

// ---------------------------------------------------------------------------
// bf16 helpers (attention)
// ---------------------------------------------------------------------------
__device__ __forceinline__ void mma_bf16_16x8x16(
    float& c0, float& c1, float& c2, float& c3,
    uint32_t a0, uint32_t a1, uint32_t a2, uint32_t a3,
    uint32_t b0, uint32_t b1)
{
    asm volatile(
        "mma.sync.aligned.m16n8k16.row.col.f32.bf16.bf16.f32 "
        "{%0,%1,%2,%3}, {%4,%5,%6,%7}, {%8,%9}, {%0,%1,%2,%3};"
        : "+f"(c0), "+f"(c1), "+f"(c2), "+f"(c3)
        : "r"(a0), "r"(a1), "r"(a2), "r"(a3), "r"(b0), "r"(b1));
}

// pack two floats (lo half = a, hi half = b) as bf16x2 bits
__device__ __forceinline__ uint32_t pack_bf16(float a, float b) {
    __nv_bfloat162 p = __floats2bfloat162_rn(a, b);
    return *reinterpret_cast<uint32_t*>(&p);
}

// split x into bf16 hi + bf16 lo (x ~= hi + lo, residual ~2^-18 |x|)
__device__ __forceinline__ void split_bf16(float x, float& h, float& l) {
    h = __bfloat162float(__float2bfloat16_rn(x));
    l = x - h;
}

// ---------------------------------------------------------------------------
// tf32 tensor-core GEMM with fused bias (unchanged from R3/R5, passing)
// ---------------------------------------------------------------------------
template<int N, int K>
__device__ __forceinline__ void gemm_tf32(
    const float* __restrict__ A, const float* __restrict__ Bw,
    const float* __restrict__ bias, float* __restrict__ C)
{
    constexpr int BM = 128, BN = 128, BK = 32;
    constexpr int AS = BK + 4;
    constexpr int BS = BN + 8;

    __shared__ uint32_t As[BM * AS];
    __shared__ uint32_t Bs[BK * BS];

    const int tid    = threadIdx.x;
    const int lane   = tid & 31;
    const int wid    = tid >> 5;
    const int warp_m = wid >> 2;
    const int warp_n = wid & 3;
    const int g      = lane >> 2;
    const int t      = lane & 3;

    const int cRow = blockIdx.y * BM;
    const int cCol = blockIdx.x * BN;

    float acc[4][4][4];
    #pragma unroll
    for (int i = 0; i < 4; i++)
        #pragma unroll
        for (int j = 0; j < 4; j++)
            #pragma unroll
            for (int r = 0; r < 4; r++) acc[i][j][r] = 0.f;

    for (int k0 = 0; k0 < K; k0 += BK) {
        #pragma unroll
        for (int i = 0; i < 4; i++) {
            int idx = i * 256 + tid;
            int m   = idx >> 3;
            int c4  = (idx & 7) * 4;
            float4 v = *reinterpret_cast<const float4*>(
                A + (long)(cRow + m) * K + k0 + c4);
            As[m * AS + c4 + 0] = f32_to_tf32(v.x);
            As[m * AS + c4 + 1] = f32_to_tf32(v.y);
            As[m * AS + c4 + 2] = f32_to_tf32(v.z);
            As[m * AS + c4 + 3] = f32_to_tf32(v.w);
        }
        #pragma unroll
        for (int i = 0; i < 4; i++) {
            int idx = i * 256 + tid;
            int kr  = idx >> 5;
            int nc  = (idx & 31) * 4;
            float4 v = *reinterpret_cast<const float4*>(
                Bw + (long)(k0 + kr) * N + cCol + nc);
            Bs[kr * BS + nc + 0] = f32_to_tf32(v.x);
            Bs[kr * BS + nc + 1] = f32_to_tf32(v.y);
            Bs[kr * BS + nc + 2] = f32_to_tf32(v.z);
            Bs[kr * BS + nc + 3] = f32_to_tf32(v.w);
        }
        __syncthreads();

        #pragma unroll
        for (int kk = 0; kk < 4; kk++) {
            const int k8 = kk * 8;
            uint32_t a[4][4];
            #pragma unroll
            for (int ma = 0; ma < 4; ma++) {
                int row = warp_m * 64 + ma * 16;
                a[ma][0] = As[(row + g) * AS + k8 + t];
                a[ma][1] = As[(row + g + 8) * AS + k8 + t];
                a[ma][2] = As[(row + g) * AS + k8 + t + 4];
                a[ma][3] = As[(row + g + 8) * AS + k8 + t + 4];
            }
            uint32_t b[4][2];
            #pragma unroll
            for (int na = 0; na < 4; na++) {
                int col = warp_n * 32 + na * 8 + g;
                b[na][0] = Bs[(k8 + t) * BS + col];
                b[na][1] = Bs[(k8 + t + 4) * BS + col];
            }
            #pragma unroll
            for (int ma = 0; ma < 4; ma++)
                #pragma unroll
                for (int na = 0; na < 4; na++)
                    mma_tf32_16x8x8(acc[ma][na][0], acc[ma][na][1],
                                    acc[ma][na][2], acc[ma][na][3],
                                    a[ma][0], a[ma][1], a[ma][2], a[ma][3],
                                    b[na][0], b[na][1]);
        }
        __syncthreads();
    }

    #pragma unroll
    for (int ma = 0; ma < 4; ma++) {
        #pragma unroll
        for (int na = 0; na < 4; na++) {
            int row = cRow + warp_m * 64 + ma * 16 + g;
            int col = cCol + warp_n * 32 + na * 8 + 2 * t;
            float2 bv = *reinterpret_cast<const float2*>(bias + col);
            float2 v0, v1;
            v0.x = acc[ma][na][0] + bv.x;
            v0.y = acc[ma][na][1] + bv.y;
            v1.x = acc[ma][na][2] + bv.x;
            v1.y = acc[ma][na][3] + bv.y;
            *reinterpret_cast<float2*>(C + (long)row * N + col)       = v0;
            *reinterpret_cast<float2*>(C + (long)(row + 8) * N + col) = v1;
        }
    }
}

__global__ __launch_bounds__(256) void qkv_tf32_kernel(
    const float* __restrict__ A, const float* __restrict__ Bw,
    const float* __restrict__ bias)
{
    gemm_tf32<QKV_N, EMB>(A, Bw, bias, g_qkv);
}

__global__ __launch_bounds__(256) void proj_tf32_kernel(
    const float* __restrict__ Bw, const float* __restrict__ bias,
    float* __restrict__ C)
{
    gemm_tf32<EMB, EMB>(g_attn, Bw, bias, C);
}

// ---------------------------------------------------------------------------
// Flash attention, bf16 split tensor cores (m16n8k16).
// Block: 256 threads (8 warps) = 128 query rows of one (b,h). Warp w owns
// rows [16w,16w+16). K/V tiles of 64 keys in smem.
//   K: pre-split bf16 (Kh,Kl), word layout [key][dim/2], stride 36 words
//      -> b-frag word bank (4g+t)%32, conflict-free.
//   V: pre-split bf16, key-paired: Vp[r][d] = bf16x2(V[2r][d], V[2r+1][d]),
//      stride 72 words -> b-frag bank (8t+g)%32, conflict-free.
// QK^T: 3-term (QhKh + QlKh + QhKl), residual ~2^-18 -> fp32-accurate logits.
// PV:   3-term; S C-fragment IS P's A-fragment for k16 bf16 -> no shuffles.
// ---------------------------------------------------------------------------
#define KW_STRIDE 36   // words per key row (32 dim-pairs + 4 pad)
#define VW_STRIDE 72   // words per key-pair row (64 dims + 8 pad)

__global__ __launch_bounds__(256) void flash_attn_mma_kernel()
{
    const int qt   = (int)gridDim.x - 1 - (int)blockIdx.x;  // heavy blocks first
    const int h    = blockIdx.y;
    const int b    = blockIdx.z;
    const int tid  = threadIdx.x;
    const int lane = tid & 31;
    const int w    = tid >> 5;
    const int g    = lane >> 2;   // 0..7
    const int t    = lane & 3;    // 0..3

    const int qbase = qt * 128;
    const int row0  = qbase + w * 16 + g;   // this thread's rows: row0, row0+8
    const int hoff  = h * HDIM;

    __shared__ uint32_t Kh[64 * KW_STRIDE];   // 9216 B
    __shared__ uint32_t Kl[64 * KW_STRIDE];   // 9216 B
    __shared__ uint32_t Vph[32 * VW_STRIDE];  // 9216 B
    __shared__ uint32_t Vpl[32 * VW_STRIDE];  // 9216 B  (total 36.9 KB)

    // ---- Q fragments: scaled by 0.125, split bf16 hi/lo, packed pairs ----
    // A-frag (m16n8k16) step kk: a0=(row0, d0,d0+1) a1=(row0+8, d0,d0+1)
    //                            a2=(row0, d1,d1+1) a3=(row0+8, d1,d1+1)
    // with d0 = 16kk+2t, d1 = d0+8.
    uint32_t qh[4][4], ql[4][4];
    {
        const long r0 = (long)(b * SEQ + row0) * QKV_N + hoff;
        const long r1 = r0 + 8L * QKV_N;
        #pragma unroll
        for (int kk = 0; kk < 4; kk++) {
            int d0 = kk * 16 + 2 * t;
            int d1 = d0 + 8;
            float hx, lx, hy, ly;
            split_bf16(g_qkv[r0 + d0] * 0.125f, hx, lx);
            split_bf16(g_qkv[r0 + d0 + 1] * 0.125f, hy, ly);
            qh[kk][0] = pack_bf16(hx, hy);  ql[kk][0] = pack_bf16(lx, ly);
            split_bf16(g_qkv[r1 + d0] * 0.125f, hx, lx);
            split_bf16(g_qkv[r1 + d0 + 1] * 0.125f, hy, ly);
            qh[kk][1] = pack_bf16(hx, hy);  ql[kk][1] = pack_bf16(lx, ly);
            split_bf16(g_qkv[r0 + d1] * 0.125f, hx, lx);
            split_bf16(g_qkv[r0 + d1 + 1] * 0.125f, hy, ly);
            qh[kk][2] = pack_bf16(hx, hy);  ql[kk][2] = pack_bf16(lx, ly);
            split_bf16(g_qkv[r1 + d1] * 0.125f, hx, lx);
            split_bf16(g_qkv[r1 + d1 + 1] * 0.125f, hy, ly);
            qh[kk][3] = pack_bf16(hx, hy);  ql[kk][3] = pack_bf16(lx, ly);
        }
    }

    float o[8][4];
    #pragma unroll
    for (int na = 0; na < 8; na++)
        #pragma unroll
        for (int e = 0; e < 4; e++) o[na][e] = 0.f;
    float m0 = -INFINITY, m1 = -INFINITY, l0 = 0.f, l1 = 0.f;

    const int ntiles = 2 * qt + 2;
    for (int kt = 0; kt < ntiles; kt++) {
        // ---- fill K: 64 rows x 16 float4-chunks, 4 items/thread ----
        #pragma unroll
        for (int i = 0; i < 4; i++) {
            int idx = i * 256 + tid;
            int j   = idx >> 4;            // key row 0..63
            int c4  = (idx & 15) * 4;      // dim 0..60
            long base = (long)(b * SEQ + kt * 64 + j) * QKV_N + hoff + c4;
            float4 kv = *reinterpret_cast<const float4*>(g_qkv + base + EMB);
            float h0, l0_, h1, l1_, h2, l2_, h3, l3_;
            split_bf16(kv.x, h0, l0_); split_bf16(kv.y, h1, l1_);
            split_bf16(kv.z, h2, l2_); split_bf16(kv.w, h3, l3_);
            int wbase = j * KW_STRIDE + c4 / 2;
            Kh[wbase + 0] = pack_bf16(h0, h1);
            Kh[wbase + 1] = pack_bf16(h2, h3);
            Kl[wbase + 0] = pack_bf16(l0_, l1_);
            Kl[wbase + 1] = pack_bf16(l2_, l3_);
        }
        // ---- fill V (key-paired): 32 pair-rows x 16 chunks, 2 items/thread ----
        #pragma unroll
        for (int i = 0; i < 2; i++) {
            int idx = i * 256 + tid;
            int jp  = idx >> 4;            // key pair 0..31
            int c4  = (idx & 15) * 4;      // dim 0..60
            long base0 = (long)(b * SEQ + kt * 64 + 2 * jp) * QKV_N + hoff + 2 * EMB + c4;
            float4 v0 = *reinterpret_cast<const float4*>(g_qkv + base0);
            float4 v1 = *reinterpret_cast<const float4*>(g_qkv + base0 + QKV_N);
            int wbase = jp * VW_STRIDE + c4;
            float ha, la, hb, lb;
            split_bf16(v0.x, ha, la); split_bf16(v1.x, hb, lb);
            Vph[wbase + 0] = pack_bf16(ha, hb); Vpl[wbase + 0] = pack_bf16(la, lb);
            split_bf16(v0.y, ha, la); split_bf16(v1.y, hb, lb);
            Vph[wbase + 1] = pack_bf16(ha, hb); Vpl[wbase + 1] = pack_bf16(la, lb);
            split_bf16(v0.z, ha, la); split_bf16(v1.z, hb, lb);
            Vph[wbase + 2] = pack_bf16(ha, hb); Vpl[wbase + 2] = pack_bf16(la, lb);
            split_bf16(v0.w, ha, la); split_bf16(v1.w, hb, lb);
            Vph[wbase + 3] = pack_bf16(ha, hb); Vpl[wbase + 3] = pack_bf16(la, lb);
        }
        __syncthreads();

        // ---- scores S = Q K^T (3-term bf16 split) ----
        float s[8][4];
        #pragma unroll
        for (int na = 0; na < 8; na++)
            #pragma unroll
            for (int e = 0; e < 4; e++) s[na][e] = 0.f;

        #pragma unroll
        for (int kk = 0; kk < 4; kk++) {
            const int w0 = kk * 8 + t;        // word col for dims 16kk+2t
            #pragma unroll
            for (int na = 0; na < 8; na++) {
                int key = na * 8 + g;
                uint32_t bh0 = Kh[key * KW_STRIDE + w0];
                uint32_t bh1 = Kh[key * KW_STRIDE + w0 + 4];
                uint32_t bl0 = Kl[key * KW_STRIDE + w0];
                uint32_t bl1 = Kl[key * KW_STRIDE + w0 + 4];
                mma_bf16_16x8x16(s[na][0], s[na][1], s[na][2], s[na][3],
                                 qh[kk][0], qh[kk][1], qh[kk][2], qh[kk][3], bh0, bh1);
                mma_bf16_16x8x16(s[na][0], s[na][1], s[na][2], s[na][3],
                                 ql[kk][0], ql[kk][1], ql[kk][2], ql[kk][3], bh0, bh1);
                mma_bf16_16x8x16(s[na][0], s[na][1], s[na][2], s[na][3],
                                 qh[kk][0], qh[kk][1], qh[kk][2], qh[kk][3], bl0, bl1);
            }
        }

        // ---- causal mask (diagonal tiles only) ----
        if (kt >= 2 * qt) {
            const int colbase = kt * 64 + 2 * t;
            #pragma unroll
            for (int na = 0; na < 8; na++) {
                int c = colbase + 8 * na;
                if (c     > row0)     s[na][0] = -INFINITY;
                if (c + 1 > row0)     s[na][1] = -INFINITY;
                if (c     > row0 + 8) s[na][2] = -INFINITY;
                if (c + 1 > row0 + 8) s[na][3] = -INFINITY;
            }
        }

        // ---- online softmax (rows row0, row0+8) ----
        float tm0 = -INFINITY, tm1 = -INFINITY;
        #pragma unroll
        for (int na = 0; na < 8; na++) {
            tm0 = fmaxf(tm0, fmaxf(s[na][0], s[na][1]));
            tm1 = fmaxf(tm1, fmaxf(s[na][2], s[na][3]));
        }
        tm0 = fmaxf(tm0, __shfl_xor_sync(0xffffffffu, tm0, 1));
        tm0 = fmaxf(tm0, __shfl_xor_sync(0xffffffffu, tm0, 2));
        tm1 = fmaxf(tm1, __shfl_xor_sync(0xffffffffu, tm1, 1));
        tm1 = fmaxf(tm1, __shfl_xor_sync(0xffffffffu, tm1, 2));

        float mn0 = fmaxf(m0, tm0), mn1 = fmaxf(m1, tm1);
        float a0 = __expf(m0 - mn0), a1 = __expf(m1 - mn1);
        l0 *= a0; l1 *= a1;
        #pragma unroll
        for (int na = 0; na < 8; na++) {
            o[na][0] *= a0; o[na][1] *= a0;
            o[na][2] *= a1; o[na][3] *= a1;
        }

        float rs0 = 0.f, rs1 = 0.f;
        #pragma unroll
        for (int na = 0; na < 8; na++) {
            s[na][0] = __expf(s[na][0] - mn0);
            s[na][1] = __expf(s[na][1] - mn0);
            s[na][2] = __expf(s[na][2] - mn1);
            s[na][3] = __expf(s[na][3] - mn1);
            rs0 += s[na][0] + s[na][1];
            rs1 += s[na][2] + s[na][3];
        }
        rs0 += __shfl_xor_sync(0xffffffffu, rs0, 1);
        rs0 += __shfl_xor_sync(0xffffffffu, rs0, 2);
        rs1 += __shfl_xor_sync(0xffffffffu, rs1, 1);
        rs1 += __shfl_xor_sync(0xffffffffu, rs1, 2);
        l0 += rs0; l1 += rs1;
        m0 = mn0; m1 = mn1;

        // ---- O += P V: S C-frag pairs ARE P's k16 A-frag. 3-term split. ----
        #pragma unroll
        for (int kk = 0; kk < 4; kk++) {
            const int n0 = 2 * kk;
            // P A-frag from C-frags of tiles n0, n0+1 (split bf16 hi/lo)
            float h0, lo0, h1, lo1;
            uint32_t ph[4], pl[4];
            split_bf16(s[n0][0], h0, lo0);  split_bf16(s[n0][1], h1, lo1);
            ph[0] = pack_bf16(h0, h1);      pl[0] = pack_bf16(lo0, lo1);
            split_bf16(s[n0][2], h0, lo0);  split_bf16(s[n0][3], h1, lo1);
            ph[1] = pack_bf16(h0, h1);      pl[1] = pack_bf16(lo0, lo1);
            split_bf16(s[n0 + 1][0], h0, lo0);  split_bf16(s[n0 + 1][1], h1, lo1);
            ph[2] = pack_bf16(h0, h1);      pl[2] = pack_bf16(lo0, lo1);
            split_bf16(s[n0 + 1][2], h0, lo0);  split_bf16(s[n0 + 1][3], h1, lo1);
            ph[3] = pack_bf16(h0, h1);      pl[3] = pack_bf16(lo0, lo1);

            const int r0w = (8 * kk + t) * VW_STRIDE;
            const int r1w = (8 * kk + t + 4) * VW_STRIDE;
            #pragma unroll
            for (int na = 0; na < 8; na++) {
                int col = na * 8 + g;
                uint32_t bh0 = Vph[r0w + col], bh1 = Vph[r1w + col];
                uint32_t bl0 = Vpl[r0w + col], bl1 = Vpl[r1w + col];
                mma_bf16_16x8x16(o[na][0], o[na][1], o[na][2], o[na][3],
                                 ph[0], ph[1], ph[2], ph[3], bh0, bh1);
                mma_bf16_16x8x16(o[na][0], o[na][1], o[na][2], o[na][3],
                                 pl[0], pl[1], pl[2], pl[3], bh0, bh1);
                mma_bf16_16x8x16(o[na][0], o[na][1], o[na][2], o[na][3],
                                 ph[0], ph[1], ph[2], ph[3], bl0, bl1);
            }
        }
        __syncthreads();   // protect K/V tiles before next iteration's fill
    }

    // ---- epilogue: normalize and store merged-head output ----
    const float inv0 = 1.f / l0, inv1 = 1.f / l1;
    const long ob0 = (long)(b * SEQ + row0) * EMB + hoff;
    const long ob1 = ob0 + 8L * EMB;
    #pragma unroll
    for (int na = 0; na < 8; na++) {
        int col = na * 8 + 2 * t;
        float2 w0 = make_float2(o[na][0] * inv0, o[na][1] * inv0);
        float2 w1 = make_float2(o[na][2] * inv1, o[na][3] * inv1);
        *reinterpret_cast<float2*>(g_attn + ob0 + col) = w0;
        *reinterpret_cast<float2*>(g_attn + ob1 + col) = w1;
    }
}

// ---------------------------------------------------------------------------
// Launch: three kernel launches, nothing else.
// ---------------------------------------------------------------------------
extern "C" void kernel_launch(void* const* d_in, const int* in_sizes, int n_in,
                              void* d_out, int out_size)
{
    const float* hidden = (const float*)d_in[0];
    const float* w_attn = (const float*)d_in[1];
    const float* b_attn = (const float*)d_in[2];
    const float* w_proj = (const float*)d_in[3];
    const float* b_proj = (const float*)d_in[4];
    float* out = (float*)d_out;

    // 1) QKV projection (tf32 TC): [4096,1024] @ [1024,3072] + bias -> g_qkv
    qkv_tf32_kernel<<<dim3(QKV_N / 128, ROWS / 128), 256>>>(hidden, w_attn, b_attn);

    // 2) Causal MHA, bf16-split MMA flash attention: g_qkv -> g_attn
    flash_attn_mma_kernel<<<dim3(SEQ / 128, HEADS, BATCH), 256>>>();

    // 3) Output projection (tf32 TC): g_attn @ [1024,1024] + bias -> out
    proj_tf32_kernel<<<dim3(EMB / 128, ROWS / 128), 256>>>(w_proj, b_proj, out);
}